// round 12
// baseline (speedup 1.0000x reference)
#include <cuda_runtime.h>
#include <cuda_fp16.h>
#include <cuda_bf16.h>
#include <math.h>
#include <stdint.h>

// ---------------- problem constants ----------------
#define BSZ   2
#define LSEQ  4096
#define TTOT  8192          // BSZ*LSEQ
#define HIDD  768
#define IF    1536          // I
#define NST   128           // N
#define HH    24            // H
#define PP    64            // P
#define CSZ   256           // chunk size
#define CN    16            // LSEQ/CSZ
#define KC    4             // conv kernel
#define NPROJ 3352          // 2*(I+N)+H
#define XBCW  1792          // I+2N

// ---------------- scratch (static device globals; no allocs) ----------------
__device__ float  g_zx[TTOT * NPROJ];               // in_proj output (z | xBC | dt)
__device__ float  g_xc[TTOT * XBCW];                // conv+silu output
__device__ float  g_dt[TTOT * HH];                  // softplus(dt+bias)
__device__ float  g_ac[BSZ * HH * CN * CSZ];        // per-chunk inclusive cumsum of A*dt
__device__ float  g_ls[BSZ * CN * HH * PP * NST];   // local chunk states
__device__ float  g_ps[BSZ * CN * HH * PP * NST];   // prefix states entering chunk
__device__ float  g_y [TTOT * IF];                  // y fp32 (pre-norm)
__device__ __half g_yh [TTOT * IF];                 // y fp16 (post-norm, out_proj A)
__device__ __half g_hsh[TTOT * HIDD];               // hs in fp16
__device__ __half g_inwT[NPROJ * HIDD];             // in_proj_w^T, fp16
__device__ __half g_owT [HIDD * IF];                // out_proj_w^T, fp16

// ---------------- helpers ----------------
__device__ __forceinline__ uint32_t fu(float x) { return __float_as_uint(x); }

__device__ __forceinline__ void mma_f16(float* c, uint32_t a0, uint32_t a1,
                                        uint32_t a2, uint32_t a3,
                                        uint32_t b0, uint32_t b1) {
    asm volatile(
        "mma.sync.aligned.m16n8k16.row.col.f32.f16.f16.f32 "
        "{%0,%1,%2,%3}, {%4,%5,%6,%7}, {%8,%9}, {%0,%1,%2,%3};\n"
        : "+f"(c[0]), "+f"(c[1]), "+f"(c[2]), "+f"(c[3])
        : "r"(a0), "r"(a1), "r"(a2), "r"(a3), "r"(b0), "r"(b1));
}
__device__ __forceinline__ void ldsm_x4(uint32_t addr, uint32_t& r0, uint32_t& r1,
                                        uint32_t& r2, uint32_t& r3) {
    asm volatile("ldmatrix.sync.aligned.m8n8.x4.shared.b16 {%0,%1,%2,%3}, [%4];"
                 : "=r"(r0), "=r"(r1), "=r"(r2), "=r"(r3) : "r"(addr));
}
__device__ __forceinline__ void cpasync16(uint32_t daddr, const void* gaddr, bool pred) {
    int sz = pred ? 16 : 0;
    asm volatile("cp.async.cg.shared.global [%0], [%1], 16, %2;"
                 :: "r"(daddr), "l"(gaddr), "r"(sz));
}
#define CP_COMMIT()  asm volatile("cp.async.commit_group;")
#define CP_WAIT3()   asm volatile("cp.async.wait_group 3;")

#define LDSM_OFF_H(S) ((uint32_t)(((lane & 7) + ((lane >> 3) & 1) * 8) * (S) + (lane >> 4) * 8))

// ================= FP16 GEMM: ldmatrix + cp.async, BK=16, 5 stages, BN=128 =================
#define GSTH 24
#define STAGE_H (128 * GSTH)
#define NSTAGE 5

__global__ __launch_bounds__(256, 2) void f16gemm_kernel(const __half* __restrict__ A,
                                                         const __half* __restrict__ Bt,
                                                         float* __restrict__ C,
                                                         int M, int N, int K) {
    extern __shared__ __half smh[];
    const int tid = threadIdx.x;
    const int lane = tid & 31;
    const int warpId = tid >> 5;
    const int gid = lane >> 2, tig = lane & 3;
    const int warpM = warpId & 1;
    const int warpN = warpId >> 1;
    const int rowBase = blockIdx.y * 128;
    const int colBase = blockIdx.x * 128;
    const int nk = K >> 4;

    uint32_t smBase = (uint32_t)__cvta_generic_to_shared(smh);

    const int cpr = tid >> 1;
    const int cpc = (tid & 1) * 8;
    const int nB = colBase + cpr;
    const bool bOK = nB < N;
    const int nBc = bOK ? nB : 0;
    const uint32_t cpOffB = (uint32_t)(cpr * GSTH + cpc) * 2;

    auto issue = [&](int kt, int stage) {
        int k0 = kt << 4;
        uint32_t sA = smBase + (uint32_t)(stage * 2 * STAGE_H) * 2 + cpOffB;
        uint32_t sB = smBase + (uint32_t)((stage * 2 + 1) * STAGE_H) * 2 + cpOffB;
        const __half* ga = &A[(size_t)(rowBase + cpr) * K + k0 + cpc];
        const __half* gb = &Bt[(size_t)nBc * K + k0 + cpc];
        cpasync16(sA, ga, true);
        cpasync16(sB, gb, bOK);
        CP_COMMIT();
    };

    const uint32_t lOff = LDSM_OFF_H(GSTH);

    float acc[4][4][4];
#pragma unroll
    for (int mt = 0; mt < 4; mt++)
#pragma unroll
        for (int nt = 0; nt < 4; nt++)
#pragma unroll
            for (int e = 0; e < 4; e++) acc[mt][nt][e] = 0.f;

#pragma unroll
    for (int p = 0; p < NSTAGE - 1; p++)
        if (p < nk) issue(p, p);

    for (int kt = 0; kt < nk; kt++) {
        CP_WAIT3();
        __syncthreads();
        if (kt + NSTAGE - 1 < nk) issue(kt + NSTAGE - 1, (kt + NSTAGE - 1) % NSTAGE);

        int stage = kt % NSTAGE;
        uint32_t aBase = smBase + (uint32_t)(stage * 2 * STAGE_H) * 2;
        uint32_t bBase = smBase + (uint32_t)((stage * 2 + 1) * STAGE_H) * 2;

        uint32_t bfr[4][2];
#pragma unroll
        for (int pair = 0; pair < 2; pair++) {
            uint32_t addr = bBase + ((uint32_t)((warpN * 32 + pair * 16) * GSTH) + lOff) * 2;
            uint32_t r0, r1, r2, r3;
            ldsm_x4(addr, r0, r1, r2, r3);
            bfr[pair * 2][0] = r0; bfr[pair * 2][1] = r2;
            bfr[pair * 2 + 1][0] = r1; bfr[pair * 2 + 1][1] = r3;
        }
#pragma unroll
        for (int mt = 0; mt < 4; mt++) {
            uint32_t addr = aBase + ((uint32_t)((warpM * 64 + mt * 16) * GSTH) + lOff) * 2;
            uint32_t a0, a1, a2, a3;
            ldsm_x4(addr, a0, a1, a2, a3);
#pragma unroll
            for (int nt = 0; nt < 4; nt++)
                mma_f16(acc[mt][nt], a0, a1, a2, a3, bfr[nt][0], bfr[nt][1]);
        }
    }

#pragma unroll
    for (int mt = 0; mt < 4; mt++) {
        int r0 = rowBase + warpM * 64 + mt * 16 + gid;
#pragma unroll
        for (int nt = 0; nt < 4; nt++) {
            int c0 = colBase + warpN * 32 + nt * 8 + tig * 2;
            if (c0 < N)     C[(size_t)r0 * N + c0]           = acc[mt][nt][0];
            if (c0 + 1 < N) C[(size_t)r0 * N + c0 + 1]       = acc[mt][nt][1];
            if (c0 < N)     C[(size_t)(r0 + 8) * N + c0]     = acc[mt][nt][2];
            if (c0 + 1 < N) C[(size_t)(r0 + 8) * N + c0 + 1] = acc[mt][nt][3];
        }
    }
}

// ---------------- prep ----------------
__global__ __launch_bounds__(256) void round_h_kernel(const float* __restrict__ src,
                                                      __half* __restrict__ dst, int n) {
    int i = blockIdx.x * 256 + threadIdx.x;
    if (i < n) dst[i] = __float2half(src[i]);
}

__global__ void transpose_round_h_kernel(const float* __restrict__ src,
                                         __half* __restrict__ dst, int R, int Cc) {
    __shared__ float t[32][33];
    int c0 = blockIdx.x * 32, r0 = blockIdx.y * 32;
    int x = c0 + threadIdx.x;
    for (int i = threadIdx.y; i < 32; i += 8) {
        int y = r0 + i;
        if (x < Cc && y < R) t[i][threadIdx.x] = src[(size_t)y * Cc + x];
    }
    __syncthreads();
    int xo = r0 + threadIdx.x;
    for (int i = threadIdx.y; i < 32; i += 8) {
        int yo = c0 + i;
        if (xo < R && yo < Cc) dst[(size_t)yo * R + xo] = __float2half(t[threadIdx.x][i]);
    }
}

// ---------------- conv1d + bias + silu: 8 timesteps per thread ----------------
// work item = (ch4, lt8): ch4 in [0,448), lt8 in [0, TTOT/8)
__global__ __launch_bounds__(256) void conv_kernel(const float* __restrict__ cw,
                                                   const float* __restrict__ cb) {
    int idx = blockIdx.x * 256 + threadIdx.x;          // < 448 * 1024
    int ch4 = idx % 448;
    int lt8 = idx / 448;
    int ch = ch4 * 4;
    int t0 = lt8 * 8;
    int b = t0 / LSEQ, l0 = t0 % LSEQ;

    float4 w[KC];
#pragma unroll
    for (int k = 0; k < KC; k++)
        w[k] = *reinterpret_cast<const float4*>(&cw[k * XBCW + ch]);
    float4 bias = *reinterpret_cast<const float4*>(&cb[ch]);

    float4 xb[11];
#pragma unroll
    for (int j = 0; j < 11; j++) {
        int lp = l0 - 3 + j;
        if (lp >= 0)
            xb[j] = *reinterpret_cast<const float4*>(&g_zx[(size_t)(b * LSEQ + lp) * NPROJ + IF + ch]);
        else
            xb[j] = make_float4(0.f, 0.f, 0.f, 0.f);
    }
#pragma unroll
    for (int i = 0; i < 8; i++) {
        float4 acc = bias;
#pragma unroll
        for (int k = 0; k < KC; k++) {
            float4 xv = xb[i + k];
            acc.x = fmaf(xv.x, w[k].x, acc.x);
            acc.y = fmaf(xv.y, w[k].y, acc.y);
            acc.z = fmaf(xv.z, w[k].z, acc.z);
            acc.w = fmaf(xv.w, w[k].w, acc.w);
        }
        acc.x = acc.x / (1.f + expf(-acc.x));
        acc.y = acc.y / (1.f + expf(-acc.y));
        acc.z = acc.z / (1.f + expf(-acc.z));
        acc.w = acc.w / (1.f + expf(-acc.w));
        *reinterpret_cast<float4*>(&g_xc[(size_t)(t0 + i) * XBCW + ch]) = acc;
    }
}

// ---------------- acum with fused dt softplus ----------------
__global__ __launch_bounds__(256) void acum_kernel(const float* __restrict__ alog,
                                                   const float* __restrict__ dtb) {
    int bx = blockIdx.x;
    int c  = bx % CN;
    int h  = (bx / CN) % HH;
    int b  = bx / (CN * HH);
    int s  = threadIdx.x;
    int t  = b * LSEQ + c * CSZ + s;
    float A = -expf(alog[h]);
    float x = g_zx[(size_t)t * NPROJ + (NPROJ - HH) + h] + dtb[h];
    float sp = (x > 0.f) ? (x + log1pf(expf(-x))) : log1pf(expf(x));
    float dtv = fmaxf(sp, 0.f);
    g_dt[(size_t)t * HH + h] = dtv;
    __shared__ float a[CSZ];
    a[s] = A * dtv;
    __syncthreads();
    for (int off = 1; off < CSZ; off <<= 1) {
        float add = (s >= off) ? a[s - off] : 0.f;
        __syncthreads();
        a[s] += add;
        __syncthreads();
    }
    g_ac[(size_t)((b * HH + h) * CN + c) * CSZ + s] = a[s];
}

// ================= chunk state via FP16 mma + ldmatrix =================
#define CS_SH 72

__global__ __launch_bounds__(256) void chunkstate_mma_kernel() {
    extern __shared__ __half smh[];
    __half* As = smh;                    // 64 x 72
    __half* Bs = smh + 64 * CS_SH;       // 128 x 72

    int bx = blockIdx.x;
    int h = bx % HH;
    int c = (bx / HH) % CN;
    int b = bx / (HH * CN);
    int tid = threadIdx.x, lane = tid & 31, warpId = tid >> 5;
    int gid = lane >> 2, tig = lane & 3;
    int warpM = warpId & 1, warpN = warpId >> 1;
    int acbase = ((b * HH + h) * CN + c) * CSZ;
    int tbase = b * LSEQ + c * CSZ;
    float Asum = g_ac[acbase + CSZ - 1];

    uint32_t smB = (uint32_t)__cvta_generic_to_shared(smh);
    uint32_t asB = smB;
    uint32_t bsB = smB + (uint32_t)(64 * CS_SH) * 2;
    const uint32_t lOff = LDSM_OFF_H(CS_SH);

    float acc[2][4][4];
#pragma unroll
    for (int mt = 0; mt < 2; mt++)
#pragma unroll
        for (int nt = 0; nt < 4; nt++)
#pragma unroll
            for (int e = 0; e < 4; e++) acc[mt][nt][e] = 0.f;

    for (int kt = 0; kt < 4; kt++) {
        for (int i = tid; i < 64 * 64; i += 256) {
            int l = i >> 6, p = i & 63;
            int ts = tbase + kt * 64 + l;
            float v = g_xc[(size_t)ts * XBCW + h * PP + p] * g_dt[(size_t)ts * HH + h];
            As[p * CS_SH + l] = __float2half(v);
        }
        for (int i = tid; i < 64 * 128; i += 256) {
            int l = i >> 7, n = i & 127;
            int ts = tbase + kt * 64 + l;
            float dec = expf(Asum - g_ac[acbase + kt * 64 + l]);
            Bs[n * CS_SH + l] = __float2half(g_xc[(size_t)ts * XBCW + IF + n] * dec);
        }
        __syncthreads();
#pragma unroll
        for (int k16 = 0; k16 < 4; k16++) {
            int k0 = k16 * 16;
            uint32_t af[2][4];
#pragma unroll
            for (int mt = 0; mt < 2; mt++)
                ldsm_x4(asB + ((uint32_t)((warpM * 32 + mt * 16) * CS_SH + k0) + lOff) * 2,
                        af[mt][0], af[mt][1], af[mt][2], af[mt][3]);
#pragma unroll
            for (int p2 = 0; p2 < 2; p2++) {
                uint32_t r0, r1, r2, r3;
                ldsm_x4(bsB + ((uint32_t)((warpN * 32 + p2 * 16) * CS_SH + k0) + lOff) * 2, r0, r1, r2, r3);
#pragma unroll
                for (int mt = 0; mt < 2; mt++) {
                    mma_f16(acc[mt][p2 * 2],     af[mt][0], af[mt][1], af[mt][2], af[mt][3], r0, r2);
                    mma_f16(acc[mt][p2 * 2 + 1], af[mt][0], af[mt][1], af[mt][2], af[mt][3], r1, r3);
                }
            }
        }
        __syncthreads();
    }

    size_t base = ((size_t)((b * CN + c) * HH + h)) * PP * NST;
#pragma unroll
    for (int mt = 0; mt < 2; mt++) {
        int p0 = warpM * 32 + mt * 16 + gid;
#pragma unroll
        for (int nt = 0; nt < 4; nt++) {
            int n0 = warpN * 32 + nt * 8 + tig * 2;
            g_ls[base + (size_t)p0 * NST + n0]           = acc[mt][nt][0];
            g_ls[base + (size_t)p0 * NST + n0 + 1]       = acc[mt][nt][1];
            g_ls[base + (size_t)(p0 + 8) * NST + n0]     = acc[mt][nt][2];
            g_ls[base + (size_t)(p0 + 8) * NST + n0 + 1] = acc[mt][nt][3];
        }
    }
}

// ---------------- inter-chunk recurrence ----------------
__global__ __launch_bounds__(256) void recur_kernel() {
    int blk = blockIdx.x;
    int seg = blk & 31;
    int bh  = blk >> 5;
    int b = bh / HH, h = bh % HH;
    int idx = seg * 256 + threadIdx.x;
    float st = 0.f;
#pragma unroll
    for (int c = 0; c < CN; c++) {
        float es = expf(g_ac[(size_t)((b * HH + h) * CN + c) * CSZ + CSZ - 1]);
        size_t base = ((size_t)((b * CN + c) * HH + h)) * PP * NST;
        g_ps[base + idx] = st;
        st = fmaf(st, es, g_ls[base + idx]);
    }
}

// ================= Y fused: one block per (b,c,h), full 256-row chunk =================
// Warp w handles rows [w*32, w*32+32); lt_w = w/2.
// accD = exp(aL) * (C @ S^T), then st-loop adds masked-decay (C@B^T) @ Xd.
#define YF_CS 136   // C stride (halves)
#define YF_BS 136   // B/S stride
#define YF_XS 72    // X stride ([p][s])
#define YF_GS 72    // G stride ([l][s])

__global__ __launch_bounds__(256) void ydiag_fused_kernel(const float* __restrict__ Darr) {
    extern __shared__ __half smh[];
    __half* Cs  = smh;                        // 256 x 136
    __half* Bst = Cs + 256 * YF_CS;           // 64 x 136 (S first, then B tiles)
    __half* Xs  = Bst + 64 * YF_BS;           // 64 x 72 ([p][s])
    __half* Gs  = Xs + 64 * YF_XS;            // 256 x 72
    float*  aL  = reinterpret_cast<float*>(Gs + 256 * YF_GS);   // 256
    float*  aS  = aL + 256;                                     // 64

    int bch = blockIdx.x;
    int h = bch % HH;
    int c = (bch / HH) % CN;
    int b = bch / (HH * CN);
    int tid = threadIdx.x, lane = tid & 31, w = tid >> 5;
    int gid = lane >> 2, tig = lane & 3;
    int rowW = w * 32;                 // warp row base within chunk
    int ltw = w >> 1;
    int acbase = ((b * HH + h) * CN + c) * CSZ;
    int tbase = b * LSEQ + c * CSZ;

    uint32_t smB = (uint32_t)__cvta_generic_to_shared(smh);
    uint32_t csB  = smB;
    uint32_t bstB = smB + (uint32_t)(256 * YF_CS) * 2;
    uint32_t xsB  = bstB + (uint32_t)(64 * YF_BS) * 2;
    uint32_t gsB  = xsB + (uint32_t)(64 * YF_XS) * 2;

    const uint32_t lOff136 = LDSM_OFF_H(YF_CS);
    const uint32_t lOff72  = LDSM_OFF_H(YF_XS);

    // ---- load C (256 x 128), aL (256), S -> Bst ----
    for (int i = tid; i < 256 * 128; i += 256) {
        int l = i >> 7, n = i & 127;
        Cs[l * YF_CS + n] = __float2half(g_xc[(size_t)(tbase + l) * XBCW + IF + NST + n]);
    }
    aL[tid] = g_ac[acbase + tid];
    {
        size_t sbase = ((size_t)((b * CN + c) * HH + h)) * PP * NST;
        for (int i = tid; i < 64 * 128; i += 256) {
            int p = i >> 7, n = i & 127;
            Bst[p * YF_BS + n] = __float2half(g_ps[sbase + (size_t)p * NST + n]);
        }
    }
    __syncthreads();

    // ---- accD = C @ S^T (K = 128) ----
    float acc[2][8][4];
#pragma unroll
    for (int mt = 0; mt < 2; mt++)
#pragma unroll
        for (int nt = 0; nt < 8; nt++)
#pragma unroll
            for (int e = 0; e < 4; e++) acc[mt][nt][e] = 0.f;

#pragma unroll
    for (int k16 = 0; k16 < 8; k16++) {
        int k0 = k16 * 16;
        uint32_t af[2][4];
#pragma unroll
        for (int mt = 0; mt < 2; mt++)
            ldsm_x4(csB + ((uint32_t)((rowW + mt * 16) * YF_CS + k0) + lOff136) * 2,
                    af[mt][0], af[mt][1], af[mt][2], af[mt][3]);
#pragma unroll
        for (int p2 = 0; p2 < 4; p2++) {
            uint32_t r0, r1, r2, r3;
            ldsm_x4(bstB + ((uint32_t)((p2 * 16) * YF_BS + k0) + lOff136) * 2, r0, r1, r2, r3);
#pragma unroll
            for (int mt = 0; mt < 2; mt++) {
                mma_f16(acc[mt][p2 * 2],     af[mt][0], af[mt][1], af[mt][2], af[mt][3], r0, r2);
                mma_f16(acc[mt][p2 * 2 + 1], af[mt][0], af[mt][1], af[mt][2], af[mt][3], r1, r3);
            }
        }
    }
    // scale by exp(aL) rowwise
#pragma unroll
    for (int mt = 0; mt < 2; mt++) {
        float eA = expf(aL[rowW + mt * 16 + gid]);
        float eB = expf(aL[rowW + mt * 16 + gid + 8]);
#pragma unroll
        for (int nt = 0; nt < 8; nt++) {
            acc[mt][nt][0] *= eA; acc[mt][nt][1] *= eA;
            acc[mt][nt][2] *= eB; acc[mt][nt][3] *= eB;
        }
    }

    // ---- st loop: acc += masked-decay(C@B^T) @ Xd ----
    for (int st = 0; st < 4; st++) {
        __syncthreads();   // all warps done with previous Bst/Xs
        for (int i = tid; i < 64 * 128; i += 256) {
            int s = i >> 7, n = i & 127;
            Bst[s * YF_BS + n] = __float2half(g_xc[(size_t)(tbase + st * 64 + s) * XBCW + IF + n]);
        }
        for (int i = tid; i < 64 * 64; i += 256) {
            int s = i >> 6, p = i & 63;
            int ts = tbase + st * 64 + s;
            Xs[p * YF_XS + s] = __float2half(g_xc[(size_t)ts * XBCW + h * PP + p] * g_dt[(size_t)ts * HH + h]);
        }
        if (tid < 64) aS[tid] = g_ac[acbase + st * 64 + tid];
        __syncthreads();

        if (st <= ltw) {
            // G per mt sequentially (keeps regs low); spill masked G to Gs (own rows)
#pragma unroll
            for (int mt = 0; mt < 2; mt++) {
                int m0 = rowW + mt * 16;
                float g4[4][4];
#pragma unroll
                for (int q = 0; q < 4; q++)
#pragma unroll
                    for (int e = 0; e < 4; e++) g4[q][e] = 0.f;
                // split 64 cols into 2 halves to bound registers: p2h covers cols p2h*32..p2h*32+31
#pragma unroll
                for (int p2h = 0; p2h < 2; p2h++) {
#pragma unroll
                    for (int q = 0; q < 4; q++)
#pragma unroll
                        for (int e = 0; e < 4; e++) g4[q][e] = 0.f;
#pragma unroll
                    for (int k16 = 0; k16 < 8; k16++) {
                        int k0 = k16 * 16;
                        uint32_t a0, a1, a2, a3;
                        ldsm_x4(csB + ((uint32_t)(m0 * YF_CS + k0) + lOff136) * 2, a0, a1, a2, a3);
#pragma unroll
                        for (int pp2 = 0; pp2 < 2; pp2++) {
                            uint32_t r0, r1, r2, r3;
                            ldsm_x4(bstB + ((uint32_t)((p2h * 32 + pp2 * 16) * YF_BS + k0) + lOff136) * 2,
                                    r0, r1, r2, r3);
                            mma_f16(g4[pp2 * 2],     a0, a1, a2, a3, r0, r2);
                            mma_f16(g4[pp2 * 2 + 1], a0, a1, a2, a3, r1, r3);
                        }
                    }
                    // mask + decay + spill
                    int lA = m0 + gid, lB = lA + 8;
                    float aLA = aL[lA], aLB = aL[lB];
#pragma unroll
                    for (int q = 0; q < 4; q++) {
                        int s0 = p2h * 32 + q * 8 + tig * 2;
                        int gs0 = st * 64 + s0;
                        float as0 = aS[s0], as1 = aS[s0 + 1];
                        float v0 = (gs0     <= lA) ? g4[q][0] * expf(aLA - as0) : 0.f;
                        float v1 = (gs0 + 1 <= lA) ? g4[q][1] * expf(aLA - as1) : 0.f;
                        float v2 = (gs0     <= lB) ? g4[q][2] * expf(aLB - as0) : 0.f;
                        float v3 = (gs0 + 1 <= lB) ? g4[q][3] * expf(aLB - as1) : 0.f;
                        *reinterpret_cast<__half2*>(&Gs[lA * YF_GS + s0]) = __floats2half2_rn(v0, v1);
                        *reinterpret_cast<__half2*>(&Gs[lB * YF_GS + s0]) = __floats2half2_rn(v2, v3);
                    }
                }
            }
            __syncwarp();
            // acc += G @ Xd (K = 64); Gs rows are warp-private
#pragma unroll
            for (int k16 = 0; k16 < 4; k16++) {
                int k0 = k16 * 16;
                uint32_t af[2][4];
#pragma unroll
                for (int mt = 0; mt < 2; mt++)
                    ldsm_x4(gsB + ((uint32_t)((rowW + mt * 16) * YF_GS + k0) + lOff72) * 2,
                            af[mt][0], af[mt][1], af[mt][2], af[mt][3]);
#pragma unroll
                for (int p2 = 0; p2 < 4; p2++) {
                    uint32_t r0, r1, r2, r3;
                    ldsm_x4(xsB + ((uint32_t)((p2 * 16) * YF_XS + k0) + lOff72) * 2, r0, r1, r2, r3);
#pragma unroll
                    for (int mt = 0; mt < 2; mt++) {
                        mma_f16(acc[mt][p2 * 2],     af[mt][0], af[mt][1], af[mt][2], af[mt][3], r0, r2);
                        mma_f16(acc[mt][p2 * 2 + 1], af[mt][0], af[mt][1], af[mt][2], af[mt][3], r1, r3);
                    }
                }
            }
        }
    }

    // ---- epilogue: y = acc + D*x ----
    float Dh = Darr[h];
#pragma unroll
    for (int mt = 0; mt < 2; mt++) {
        int lA = rowW + mt * 16 + gid;
        int tA = tbase + lA, tB = tA + 8;
#pragma unroll
        for (int nt = 0; nt < 8; nt++) {
            int p0 = nt * 8 + tig * 2;
            float xA0 = g_xc[(size_t)tA * XBCW + h * PP + p0];
            float xA1 = g_xc[(size_t)tA * XBCW + h * PP + p0 + 1];
            float xB0 = g_xc[(size_t)tB * XBCW + h * PP + p0];
            float xB1 = g_xc[(size_t)tB * XBCW + h * PP + p0 + 1];
            g_y[(size_t)tA * IF + h * PP + p0]     = acc[mt][nt][0] + Dh * xA0;
            g_y[(size_t)tA * IF + h * PP + p0 + 1] = acc[mt][nt][1] + Dh * xA1;
            g_y[(size_t)tB * IF + h * PP + p0]     = acc[mt][nt][2] + Dh * xB0;
            g_y[(size_t)tB * IF + h * PP + p0 + 1] = acc[mt][nt][3] + Dh * xB1;
        }
    }
}

// ---------------- gated RMSNorm (float4 in, fp16 out) ----------------
__global__ __launch_bounds__(128) void gnorm_kernel(const float* __restrict__ nw) {
    int t = blockIdx.x;
    int tid = threadIdx.x;
    float4 v[3];
    float ss = 0.f;
#pragma unroll
    for (int k = 0; k < 3; k++) {
        int i = (tid + k * 128) * 4;
        float4 y = *reinterpret_cast<const float4*>(&g_y[(size_t)t * IF + i]);
        float4 z = *reinterpret_cast<const float4*>(&g_zx[(size_t)t * NPROJ + i]);
        float x0 = y.x * (z.x / (1.f + expf(-z.x)));
        float x1 = y.y * (z.y / (1.f + expf(-z.y)));
        float x2 = y.z * (z.z / (1.f + expf(-z.z)));
        float x3 = y.w * (z.w / (1.f + expf(-z.w)));
        v[k] = make_float4(x0, x1, x2, x3);
        ss += x0 * x0 + x1 * x1 + x2 * x2 + x3 * x3;
    }
    __shared__ float red[128];
    __shared__ float s_scale;
    red[tid] = ss;
    __syncthreads();
    for (int o = 64; o > 0; o >>= 1) {
        if (tid < o) red[tid] += red[tid + o];
        __syncthreads();
    }
    if (tid == 0) s_scale = rsqrtf(red[0] / (float)IF + 1e-5f);
    __syncthreads();
    float sc = s_scale;
#pragma unroll
    for (int k = 0; k < 3; k++) {
        int i = (tid + k * 128) * 4;
        float4 w = *reinterpret_cast<const float4*>(&nw[i]);
        __half2 h0 = __floats2half2_rn(v[k].x * sc * w.x, v[k].y * sc * w.y);
        __half2 h1 = __floats2half2_rn(v[k].z * sc * w.z, v[k].w * sc * w.w);
        *reinterpret_cast<__half2*>(&g_yh[(size_t)t * IF + i])     = h0;
        *reinterpret_cast<__half2*>(&g_yh[(size_t)t * IF + i + 2]) = h1;
    }
}

// ---------------- host launcher ----------------
extern "C" void kernel_launch(void* const* d_in, const int* in_sizes, int n_in,
                              void* d_out, int out_size) {
    const float* hs   = (const float*)d_in[0];
    const float* inw  = (const float*)d_in[1];
    const float* cw   = (const float*)d_in[2];
    const float* cb   = (const float*)d_in[3];
    const float* dtb  = (const float*)d_in[4];
    const float* alog = (const float*)d_in[5];
    const float* Dp   = (const float*)d_in[6];
    const float* nw   = (const float*)d_in[7];
    const float* ow   = (const float*)d_in[8];
    float* out = (float*)d_out;

    void *p_zx = nullptr, *p_yh = nullptr, *p_hsh = nullptr, *p_inwT = nullptr, *p_owT = nullptr;
    cudaGetSymbolAddress(&p_zx, g_zx);
    cudaGetSymbolAddress(&p_yh, g_yh);
    cudaGetSymbolAddress(&p_hsh, g_hsh);
    cudaGetSymbolAddress(&p_inwT, g_inwT);
    cudaGetSymbolAddress(&p_owT, g_owT);

    int smem_gemm = NSTAGE * 2 * STAGE_H * 2;                 // 61440
    int smem_cs = (64 * CS_SH + 128 * CS_SH) * 2;             // 27648
    int smem_yf = (256 * YF_CS + 64 * YF_BS + 64 * YF_XS + 256 * YF_GS) * 2 + (256 + 64) * 4; // ~134.4KB
    cudaFuncSetAttribute(f16gemm_kernel, cudaFuncAttributeMaxDynamicSharedMemorySize, smem_gemm);
    cudaFuncSetAttribute(chunkstate_mma_kernel, cudaFuncAttributeMaxDynamicSharedMemorySize, smem_cs);
    cudaFuncSetAttribute(ydiag_fused_kernel, cudaFuncAttributeMaxDynamicSharedMemorySize, smem_yf);

    // 0. prep
    round_h_kernel<<<(TTOT * HIDD + 255) / 256, 256>>>(hs, (__half*)p_hsh, TTOT * HIDD);
    {
        dim3 g((NPROJ + 31) / 32, (HIDD + 31) / 32);
        transpose_round_h_kernel<<<g, dim3(32, 8)>>>(inw, (__half*)p_inwT, HIDD, NPROJ);
    }
    {
        dim3 g((HIDD + 31) / 32, (IF + 31) / 32);
        transpose_round_h_kernel<<<g, dim3(32, 8)>>>(ow, (__half*)p_owT, IF, HIDD);
    }

    // 1. in_proj GEMM (fp16)
    {
        dim3 grid((NPROJ + 127) / 128, TTOT / 128);
        f16gemm_kernel<<<grid, 256, smem_gemm>>>((const __half*)p_hsh, (const __half*)p_inwT,
                                                 (float*)p_zx, TTOT, NPROJ, HIDD);
    }
    // 2. conv + silu (8 timesteps/thread)
    conv_kernel<<<(448 * (TTOT / 8)) / 256, 256>>>(cw, cb);
    // 3. cumsum with fused dt softplus
    acum_kernel<<<BSZ * HH * CN, 256>>>(alog, dtb);
    // 4. local chunk states (fp16 mma)
    chunkstate_mma_kernel<<<BSZ * CN * HH, 256, smem_cs>>>();
    // 5. inter-chunk recurrence
    recur_kernel<<<BSZ * HH * 32, 256>>>();
    // 6. Y fused (fp16 mma, one block per chunk)
    ydiag_fused_kernel<<<BSZ * CN * HH, 256, smem_yf>>>(Dp);
    // 7. gated RMSNorm (fp16 out)
    gnorm_kernel<<<TTOT, 128>>>(nw);
    // 8. out_proj GEMM (fp16)
    {
        dim3 grid(HIDD / 128, TTOT / 128);
        f16gemm_kernel<<<grid, 256, smem_gemm>>>((const __half*)p_yh, (const __half*)p_owT,
                                                 out, TTOT, HIDD, IF);
    }
}

// round 13
// speedup vs baseline: 1.2816x; 1.2816x over previous
#include <cuda_runtime.h>
#include <cuda_fp16.h>
#include <cuda_bf16.h>
#include <math.h>
#include <stdint.h>

// ---------------- problem constants ----------------
#define BSZ   2
#define LSEQ  4096
#define TTOT  8192          // BSZ*LSEQ
#define HIDD  768
#define IF    1536          // I
#define NST   128           // N
#define HH    24            // H
#define PP    64            // P
#define CSZ   256           // chunk size
#define CN    16            // LSEQ/CSZ
#define KC    4             // conv kernel
#define NPROJ 3352          // 2*(I+N)+H
#define XBCW  1792          // I+2N

// ---------------- scratch (static device globals; no allocs) ----------------
__device__ float  g_zx[TTOT * NPROJ];               // in_proj output (z | xBC | dt)
__device__ float  g_xc[TTOT * XBCW];                // conv+silu output
__device__ float  g_dt[TTOT * HH];                  // softplus(dt+bias)
__device__ float  g_ac[BSZ * HH * CN * CSZ];        // per-chunk inclusive cumsum of A*dt
__device__ float  g_ls[BSZ * CN * HH * PP * NST];   // local chunk states
__device__ float  g_ps[BSZ * CN * HH * PP * NST];   // prefix states entering chunk
__device__ float  g_y [TTOT * IF];                  // y fp32 (pre-norm)
__device__ __half g_yh [TTOT * IF];                 // y fp16 (post-norm, out_proj A)
__device__ __half g_hsh[TTOT * HIDD];               // hs in fp16
__device__ __half g_inwT[NPROJ * HIDD];             // in_proj_w^T, fp16
__device__ __half g_owT [HIDD * IF];                // out_proj_w^T, fp16

// ---------------- helpers ----------------
__device__ __forceinline__ uint32_t fu(float x) { return __float_as_uint(x); }

__device__ __forceinline__ void mma_f16(float* c, uint32_t a0, uint32_t a1,
                                        uint32_t a2, uint32_t a3,
                                        uint32_t b0, uint32_t b1) {
    asm volatile(
        "mma.sync.aligned.m16n8k16.row.col.f32.f16.f16.f32 "
        "{%0,%1,%2,%3}, {%4,%5,%6,%7}, {%8,%9}, {%0,%1,%2,%3};\n"
        : "+f"(c[0]), "+f"(c[1]), "+f"(c[2]), "+f"(c[3])
        : "r"(a0), "r"(a1), "r"(a2), "r"(a3), "r"(b0), "r"(b1));
}
__device__ __forceinline__ void ldsm_x4(uint32_t addr, uint32_t& r0, uint32_t& r1,
                                        uint32_t& r2, uint32_t& r3) {
    asm volatile("ldmatrix.sync.aligned.m8n8.x4.shared.b16 {%0,%1,%2,%3}, [%4];"
                 : "=r"(r0), "=r"(r1), "=r"(r2), "=r"(r3) : "r"(addr));
}
__device__ __forceinline__ void cpasync16(uint32_t daddr, const void* gaddr, bool pred) {
    int sz = pred ? 16 : 0;
    asm volatile("cp.async.cg.shared.global [%0], [%1], 16, %2;"
                 :: "r"(daddr), "l"(gaddr), "r"(sz));
}
#define CP_COMMIT()  asm volatile("cp.async.commit_group;")
#define CP_WAIT3()   asm volatile("cp.async.wait_group 3;")

#define LDSM_OFF_H(S) ((uint32_t)(((lane & 7) + ((lane >> 3) & 1) * 8) * (S) + (lane >> 4) * 8))

// ================= FP16 GEMM: ldmatrix + cp.async, BK=16, 5 stages, BN=128 =================
#define GSTH 24
#define STAGE_H (128 * GSTH)
#define NSTAGE 5

__global__ __launch_bounds__(256, 2) void f16gemm_kernel(const __half* __restrict__ A,
                                                         const __half* __restrict__ Bt,
                                                         float* __restrict__ C,
                                                         int M, int N, int K) {
    extern __shared__ __half smh[];
    const int tid = threadIdx.x;
    const int lane = tid & 31;
    const int warpId = tid >> 5;
    const int gid = lane >> 2, tig = lane & 3;
    const int warpM = warpId & 1;
    const int warpN = warpId >> 1;
    const int rowBase = blockIdx.y * 128;
    const int colBase = blockIdx.x * 128;
    const int nk = K >> 4;

    uint32_t smBase = (uint32_t)__cvta_generic_to_shared(smh);

    const int cpr = tid >> 1;
    const int cpc = (tid & 1) * 8;
    const int nB = colBase + cpr;
    const bool bOK = nB < N;
    const int nBc = bOK ? nB : 0;
    const uint32_t cpOffB = (uint32_t)(cpr * GSTH + cpc) * 2;

    auto issue = [&](int kt, int stage) {
        int k0 = kt << 4;
        uint32_t sA = smBase + (uint32_t)(stage * 2 * STAGE_H) * 2 + cpOffB;
        uint32_t sB = smBase + (uint32_t)((stage * 2 + 1) * STAGE_H) * 2 + cpOffB;
        const __half* ga = &A[(size_t)(rowBase + cpr) * K + k0 + cpc];
        const __half* gb = &Bt[(size_t)nBc * K + k0 + cpc];
        cpasync16(sA, ga, true);
        cpasync16(sB, gb, bOK);
        CP_COMMIT();
    };

    const uint32_t lOff = LDSM_OFF_H(GSTH);

    float acc[4][4][4];
#pragma unroll
    for (int mt = 0; mt < 4; mt++)
#pragma unroll
        for (int nt = 0; nt < 4; nt++)
#pragma unroll
            for (int e = 0; e < 4; e++) acc[mt][nt][e] = 0.f;

#pragma unroll
    for (int p = 0; p < NSTAGE - 1; p++)
        if (p < nk) issue(p, p);

    for (int kt = 0; kt < nk; kt++) {
        CP_WAIT3();
        __syncthreads();
        if (kt + NSTAGE - 1 < nk) issue(kt + NSTAGE - 1, (kt + NSTAGE - 1) % NSTAGE);

        int stage = kt % NSTAGE;
        uint32_t aBase = smBase + (uint32_t)(stage * 2 * STAGE_H) * 2;
        uint32_t bBase = smBase + (uint32_t)((stage * 2 + 1) * STAGE_H) * 2;

        uint32_t bfr[4][2];
#pragma unroll
        for (int pair = 0; pair < 2; pair++) {
            uint32_t addr = bBase + ((uint32_t)((warpN * 32 + pair * 16) * GSTH) + lOff) * 2;
            uint32_t r0, r1, r2, r3;
            ldsm_x4(addr, r0, r1, r2, r3);
            bfr[pair * 2][0] = r0; bfr[pair * 2][1] = r2;
            bfr[pair * 2 + 1][0] = r1; bfr[pair * 2 + 1][1] = r3;
        }
#pragma unroll
        for (int mt = 0; mt < 4; mt++) {
            uint32_t addr = aBase + ((uint32_t)((warpM * 64 + mt * 16) * GSTH) + lOff) * 2;
            uint32_t a0, a1, a2, a3;
            ldsm_x4(addr, a0, a1, a2, a3);
#pragma unroll
            for (int nt = 0; nt < 4; nt++)
                mma_f16(acc[mt][nt], a0, a1, a2, a3, bfr[nt][0], bfr[nt][1]);
        }
    }

#pragma unroll
    for (int mt = 0; mt < 4; mt++) {
        int r0 = rowBase + warpM * 64 + mt * 16 + gid;
#pragma unroll
        for (int nt = 0; nt < 4; nt++) {
            int c0 = colBase + warpN * 32 + nt * 8 + tig * 2;
            if (c0 < N)     C[(size_t)r0 * N + c0]           = acc[mt][nt][0];
            if (c0 + 1 < N) C[(size_t)r0 * N + c0 + 1]       = acc[mt][nt][1];
            if (c0 < N)     C[(size_t)(r0 + 8) * N + c0]     = acc[mt][nt][2];
            if (c0 + 1 < N) C[(size_t)(r0 + 8) * N + c0 + 1] = acc[mt][nt][3];
        }
    }
}

// ---------------- prep ----------------
__global__ __launch_bounds__(256) void round_h_kernel(const float* __restrict__ src,
                                                      __half* __restrict__ dst, int n) {
    int i = blockIdx.x * 256 + threadIdx.x;
    if (i < n) dst[i] = __float2half(src[i]);
}

__global__ void transpose_round_h_kernel(const float* __restrict__ src,
                                         __half* __restrict__ dst, int R, int Cc) {
    __shared__ float t[32][33];
    int c0 = blockIdx.x * 32, r0 = blockIdx.y * 32;
    int x = c0 + threadIdx.x;
    for (int i = threadIdx.y; i < 32; i += 8) {
        int y = r0 + i;
        if (x < Cc && y < R) t[i][threadIdx.x] = src[(size_t)y * Cc + x];
    }
    __syncthreads();
    int xo = r0 + threadIdx.x;
    for (int i = threadIdx.y; i < 32; i += 8) {
        int yo = c0 + i;
        if (xo < R && yo < Cc) dst[(size_t)yo * R + xo] = __float2half(t[threadIdx.x][i]);
    }
}

// ---------------- conv1d + bias + silu: 8 timesteps per thread ----------------
__global__ __launch_bounds__(256) void conv_kernel(const float* __restrict__ cw,
                                                   const float* __restrict__ cb) {
    int idx = blockIdx.x * 256 + threadIdx.x;          // < 448 * 1024
    int ch4 = idx % 448;
    int lt8 = idx / 448;
    int ch = ch4 * 4;
    int t0 = lt8 * 8;
    int b = t0 / LSEQ, l0 = t0 % LSEQ;

    float4 w[KC];
#pragma unroll
    for (int k = 0; k < KC; k++)
        w[k] = *reinterpret_cast<const float4*>(&cw[k * XBCW + ch]);
    float4 bias = *reinterpret_cast<const float4*>(&cb[ch]);

    float4 xb[11];
#pragma unroll
    for (int j = 0; j < 11; j++) {
        int lp = l0 - 3 + j;
        if (lp >= 0)
            xb[j] = *reinterpret_cast<const float4*>(&g_zx[(size_t)(b * LSEQ + lp) * NPROJ + IF + ch]);
        else
            xb[j] = make_float4(0.f, 0.f, 0.f, 0.f);
    }
#pragma unroll
    for (int i = 0; i < 8; i++) {
        float4 acc = bias;
#pragma unroll
        for (int k = 0; k < KC; k++) {
            float4 xv = xb[i + k];
            acc.x = fmaf(xv.x, w[k].x, acc.x);
            acc.y = fmaf(xv.y, w[k].y, acc.y);
            acc.z = fmaf(xv.z, w[k].z, acc.z);
            acc.w = fmaf(xv.w, w[k].w, acc.w);
        }
        acc.x = acc.x / (1.f + expf(-acc.x));
        acc.y = acc.y / (1.f + expf(-acc.y));
        acc.z = acc.z / (1.f + expf(-acc.z));
        acc.w = acc.w / (1.f + expf(-acc.w));
        *reinterpret_cast<float4*>(&g_xc[(size_t)(t0 + i) * XBCW + ch]) = acc;
    }
}

// ---------------- acum with fused dt softplus ----------------
__global__ __launch_bounds__(256) void acum_kernel(const float* __restrict__ alog,
                                                   const float* __restrict__ dtb) {
    int bx = blockIdx.x;
    int c  = bx % CN;
    int h  = (bx / CN) % HH;
    int b  = bx / (CN * HH);
    int s  = threadIdx.x;
    int t  = b * LSEQ + c * CSZ + s;
    float A = -expf(alog[h]);
    float x = g_zx[(size_t)t * NPROJ + (NPROJ - HH) + h] + dtb[h];
    float sp = (x > 0.f) ? (x + log1pf(expf(-x))) : log1pf(expf(x));
    float dtv = fmaxf(sp, 0.f);
    g_dt[(size_t)t * HH + h] = dtv;
    __shared__ float a[CSZ];
    a[s] = A * dtv;
    __syncthreads();
    for (int off = 1; off < CSZ; off <<= 1) {
        float add = (s >= off) ? a[s - off] : 0.f;
        __syncthreads();
        a[s] += add;
        __syncthreads();
    }
    g_ac[(size_t)((b * HH + h) * CN + c) * CSZ + s] = a[s];
}

// ================= chunk state via FP16 mma + ldmatrix =================
#define CS_SH 72

__global__ __launch_bounds__(256) void chunkstate_mma_kernel() {
    extern __shared__ __half smh[];
    __half* As = smh;                    // 64 x 72
    __half* Bs = smh + 64 * CS_SH;       // 128 x 72

    int bx = blockIdx.x;
    int h = bx % HH;
    int c = (bx / HH) % CN;
    int b = bx / (HH * CN);
    int tid = threadIdx.x, lane = tid & 31, warpId = tid >> 5;
    int gid = lane >> 2, tig = lane & 3;
    int warpM = warpId & 1, warpN = warpId >> 1;
    int acbase = ((b * HH + h) * CN + c) * CSZ;
    int tbase = b * LSEQ + c * CSZ;
    float Asum = g_ac[acbase + CSZ - 1];

    uint32_t smB = (uint32_t)__cvta_generic_to_shared(smh);
    uint32_t asB = smB;
    uint32_t bsB = smB + (uint32_t)(64 * CS_SH) * 2;
    const uint32_t lOff = LDSM_OFF_H(CS_SH);

    float acc[2][4][4];
#pragma unroll
    for (int mt = 0; mt < 2; mt++)
#pragma unroll
        for (int nt = 0; nt < 4; nt++)
#pragma unroll
            for (int e = 0; e < 4; e++) acc[mt][nt][e] = 0.f;

    for (int kt = 0; kt < 4; kt++) {
        for (int i = tid; i < 64 * 64; i += 256) {
            int l = i >> 6, p = i & 63;
            int ts = tbase + kt * 64 + l;
            float v = g_xc[(size_t)ts * XBCW + h * PP + p] * g_dt[(size_t)ts * HH + h];
            As[p * CS_SH + l] = __float2half(v);
        }
        for (int i = tid; i < 64 * 128; i += 256) {
            int l = i >> 7, n = i & 127;
            int ts = tbase + kt * 64 + l;
            float dec = expf(Asum - g_ac[acbase + kt * 64 + l]);
            Bs[n * CS_SH + l] = __float2half(g_xc[(size_t)ts * XBCW + IF + n] * dec);
        }
        __syncthreads();
#pragma unroll
        for (int k16 = 0; k16 < 4; k16++) {
            int k0 = k16 * 16;
            uint32_t af[2][4];
#pragma unroll
            for (int mt = 0; mt < 2; mt++)
                ldsm_x4(asB + ((uint32_t)((warpM * 32 + mt * 16) * CS_SH + k0) + lOff) * 2,
                        af[mt][0], af[mt][1], af[mt][2], af[mt][3]);
#pragma unroll
            for (int p2 = 0; p2 < 2; p2++) {
                uint32_t r0, r1, r2, r3;
                ldsm_x4(bsB + ((uint32_t)((warpN * 32 + p2 * 16) * CS_SH + k0) + lOff) * 2, r0, r1, r2, r3);
#pragma unroll
                for (int mt = 0; mt < 2; mt++) {
                    mma_f16(acc[mt][p2 * 2],     af[mt][0], af[mt][1], af[mt][2], af[mt][3], r0, r2);
                    mma_f16(acc[mt][p2 * 2 + 1], af[mt][0], af[mt][1], af[mt][2], af[mt][3], r1, r3);
                }
            }
        }
        __syncthreads();
    }

    size_t base = ((size_t)((b * CN + c) * HH + h)) * PP * NST;
#pragma unroll
    for (int mt = 0; mt < 2; mt++) {
        int p0 = warpM * 32 + mt * 16 + gid;
#pragma unroll
        for (int nt = 0; nt < 4; nt++) {
            int n0 = warpN * 32 + nt * 8 + tig * 2;
            g_ls[base + (size_t)p0 * NST + n0]           = acc[mt][nt][0];
            g_ls[base + (size_t)p0 * NST + n0 + 1]       = acc[mt][nt][1];
            g_ls[base + (size_t)(p0 + 8) * NST + n0]     = acc[mt][nt][2];
            g_ls[base + (size_t)(p0 + 8) * NST + n0 + 1] = acc[mt][nt][3];
        }
    }
}

// ---------------- inter-chunk recurrence ----------------
__global__ __launch_bounds__(256) void recur_kernel() {
    int blk = blockIdx.x;
    int seg = blk & 31;
    int bh  = blk >> 5;
    int b = bh / HH, h = bh % HH;
    int idx = seg * 256 + threadIdx.x;
    float st = 0.f;
#pragma unroll
    for (int c = 0; c < CN; c++) {
        float es = expf(g_ac[(size_t)((b * HH + h) * CN + c) * CSZ + CSZ - 1]);
        size_t base = ((size_t)((b * CN + c) * HH + h)) * PP * NST;
        g_ps[base + idx] = st;
        st = fmaf(st, es, g_ls[base + idx]);
    }
}

// ================= Y via FP16 mma + ldmatrix (round-10 best) =================
#define YH_CS 136
#define YH_XS 72
#define YH_GS 72
#define YD_HALVES (64 * YH_CS * 2 + 64 * YH_XS + 64 * YH_GS)

__global__ __launch_bounds__(256) void ydiag_mma_kernel(const float* __restrict__ Darr) {
    extern __shared__ __half smh[];
    __half* Cs  = smh;                        // 64 x 136
    __half* Bst = Cs + 64 * YH_CS;            // 64 x 136
    __half* Xs  = Bst + 64 * YH_CS;           // 64 x 72 ([p][s])
    __half* Gs  = Xs + 64 * YH_XS;            // 64 x 72
    float* aL  = reinterpret_cast<float*>(Gs + 64 * YH_GS);
    float* aS  = aL + 64;

    int lt  = blockIdx.x;
    int bch = blockIdx.y;
    int h = bch % HH;
    int c = (bch / HH) % CN;
    int b = bch / (HH * CN);
    int tid = threadIdx.x, lane = tid & 31, warpId = tid >> 5;
    int gid = lane >> 2, tig = lane & 3;
    int m0 = (warpId & 3) * 16;
    int n0 = (warpId >> 2) * 32;
    int acbase = ((b * HH + h) * CN + c) * CSZ;
    int tbase = b * LSEQ + c * CSZ;

    uint32_t smB = (uint32_t)__cvta_generic_to_shared(smh);
    uint32_t csB  = smB;
    uint32_t bstB = smB + (uint32_t)(64 * YH_CS) * 2;
    uint32_t xsB  = bstB + (uint32_t)(64 * YH_CS) * 2;
    uint32_t gsB  = xsB + (uint32_t)(64 * YH_XS) * 2;

    const uint32_t lOff136 = LDSM_OFF_H(YH_CS);
    const uint32_t lOff72  = LDSM_OFF_H(YH_XS);

    for (int i = tid; i < 64 * 128; i += 256) {
        int l = i >> 7, n = i & 127;
        Cs[l * YH_CS + n] = __float2half(g_xc[(size_t)(tbase + lt * 64 + l) * XBCW + IF + NST + n]);
    }
    if (tid < 64) aL[tid] = g_ac[acbase + lt * 64 + tid];

    float accD[4][4];
#pragma unroll
    for (int nt = 0; nt < 4; nt++)
#pragma unroll
        for (int e = 0; e < 4; e++) accD[nt][e] = 0.f;

    for (int st = 0; st <= lt; st++) {
        __syncthreads();
        for (int i = tid; i < 64 * 128; i += 256) {
            int s = i >> 7, n = i & 127;
            Bst[s * YH_CS + n] = __float2half(g_xc[(size_t)(tbase + st * 64 + s) * XBCW + IF + n]);
        }
        for (int i = tid; i < 64 * 64; i += 256) {
            int s = i >> 6, p = i & 63;
            int ts = tbase + st * 64 + s;
            Xs[p * YH_XS + s] = __float2half(g_xc[(size_t)ts * XBCW + h * PP + p] * g_dt[(size_t)ts * HH + h]);
        }
        if (tid < 64) aS[tid] = g_ac[acbase + st * 64 + tid];
        __syncthreads();

        float g4[4][4];
#pragma unroll
        for (int nt = 0; nt < 4; nt++)
#pragma unroll
            for (int e = 0; e < 4; e++) g4[nt][e] = 0.f;
#pragma unroll
        for (int k16 = 0; k16 < 8; k16++) {
            int k0 = k16 * 16;
            uint32_t a0, a1, a2, a3;
            ldsm_x4(csB + ((uint32_t)(m0 * YH_CS + k0) + lOff136) * 2, a0, a1, a2, a3);
#pragma unroll
            for (int p2 = 0; p2 < 2; p2++) {
                uint32_t r0, r1, r2, r3;
                ldsm_x4(bstB + ((uint32_t)((n0 + p2 * 16) * YH_CS + k0) + lOff136) * 2, r0, r1, r2, r3);
                mma_f16(g4[p2 * 2],     a0, a1, a2, a3, r0, r2);
                mma_f16(g4[p2 * 2 + 1], a0, a1, a2, a3, r1, r3);
            }
        }
        {
            int lA = m0 + gid, lB = lA + 8;
            int glA = lt * 64 + lA, glB = glA + 8;
            float aLA = aL[lA], aLB = aL[lB];
#pragma unroll
            for (int nt = 0; nt < 4; nt++) {
                int s0 = n0 + nt * 8 + tig * 2;
                int gs0 = st * 64 + s0;
                float as0 = aS[s0], as1 = aS[s0 + 1];
                float v0 = (gs0     <= glA) ? g4[nt][0] * expf(aLA - as0) : 0.f;
                float v1 = (gs0 + 1 <= glA) ? g4[nt][1] * expf(aLA - as1) : 0.f;
                float v2 = (gs0     <= glB) ? g4[nt][2] * expf(aLB - as0) : 0.f;
                float v3 = (gs0 + 1 <= glB) ? g4[nt][3] * expf(aLB - as1) : 0.f;
                *reinterpret_cast<__half2*>(&Gs[lA * YH_GS + s0]) = __floats2half2_rn(v0, v1);
                *reinterpret_cast<__half2*>(&Gs[lB * YH_GS + s0]) = __floats2half2_rn(v2, v3);
            }
        }
        __syncthreads();
#pragma unroll
        for (int k16 = 0; k16 < 4; k16++) {
            int k0 = k16 * 16;
            uint32_t a0, a1, a2, a3;
            ldsm_x4(gsB + ((uint32_t)(m0 * YH_GS + k0) + lOff72) * 2, a0, a1, a2, a3);
#pragma unroll
            for (int p2 = 0; p2 < 2; p2++) {
                uint32_t r0, r1, r2, r3;
                ldsm_x4(xsB + ((uint32_t)((n0 + p2 * 16) * YH_XS + k0) + lOff72) * 2, r0, r1, r2, r3);
                mma_f16(accD[p2 * 2],     a0, a1, a2, a3, r0, r2);
                mma_f16(accD[p2 * 2 + 1], a0, a1, a2, a3, r1, r3);
            }
        }
    }

    __syncthreads();
    {
        size_t sbase = ((size_t)((b * CN + c) * HH + h)) * PP * NST;
        for (int i = tid; i < 64 * 128; i += 256) {
            int p = i >> 7, n = i & 127;
            Bst[p * YH_CS + n] = __float2half(g_ps[sbase + (size_t)p * NST + n]);
        }
    }
    __syncthreads();
    float off4[4][4];
#pragma unroll
    for (int nt = 0; nt < 4; nt++)
#pragma unroll
        for (int e = 0; e < 4; e++) off4[nt][e] = 0.f;
#pragma unroll
    for (int k16 = 0; k16 < 8; k16++) {
        int k0 = k16 * 16;
        uint32_t a0, a1, a2, a3;
        ldsm_x4(csB + ((uint32_t)(m0 * YH_CS + k0) + lOff136) * 2, a0, a1, a2, a3);
#pragma unroll
        for (int p2 = 0; p2 < 2; p2++) {
            uint32_t r0, r1, r2, r3;
            ldsm_x4(bstB + ((uint32_t)((n0 + p2 * 16) * YH_CS + k0) + lOff136) * 2, r0, r1, r2, r3);
            mma_f16(off4[p2 * 2],     a0, a1, a2, a3, r0, r2);
            mma_f16(off4[p2 * 2 + 1], a0, a1, a2, a3, r1, r3);
        }
    }

    {
        int lA = m0 + gid, lB = lA + 8;
        float e0 = expf(aL[lA]), e1 = expf(aL[lB]);
        float Dh = Darr[h];
        int tA = tbase + lt * 64 + lA;
        int tB = tbase + lt * 64 + lB;
#pragma unroll
        for (int nt = 0; nt < 4; nt++) {
            int p0 = n0 + nt * 8 + tig * 2;
            float xA0 = g_xc[(size_t)tA * XBCW + h * PP + p0];
            float xA1 = g_xc[(size_t)tA * XBCW + h * PP + p0 + 1];
            float xB0 = g_xc[(size_t)tB * XBCW + h * PP + p0];
            float xB1 = g_xc[(size_t)tB * XBCW + h * PP + p0 + 1];
            g_y[(size_t)tA * IF + h * PP + p0]     = accD[nt][0] + e0 * off4[nt][0] + Dh * xA0;
            g_y[(size_t)tA * IF + h * PP + p0 + 1] = accD[nt][1] + e0 * off4[nt][1] + Dh * xA1;
            g_y[(size_t)tB * IF + h * PP + p0]     = accD[nt][2] + e1 * off4[nt][2] + Dh * xB0;
            g_y[(size_t)tB * IF + h * PP + p0 + 1] = accD[nt][3] + e1 * off4[nt][3] + Dh * xB1;
        }
    }
}

// ---------------- gated RMSNorm (float4 in, fp16 out) ----------------
__global__ __launch_bounds__(128) void gnorm_kernel(const float* __restrict__ nw) {
    int t = blockIdx.x;
    int tid = threadIdx.x;
    float4 v[3];
    float ss = 0.f;
#pragma unroll
    for (int k = 0; k < 3; k++) {
        int i = (tid + k * 128) * 4;
        float4 y = *reinterpret_cast<const float4*>(&g_y[(size_t)t * IF + i]);
        float4 z = *reinterpret_cast<const float4*>(&g_zx[(size_t)t * NPROJ + i]);
        float x0 = y.x * (z.x / (1.f + expf(-z.x)));
        float x1 = y.y * (z.y / (1.f + expf(-z.y)));
        float x2 = y.z * (z.z / (1.f + expf(-z.z)));
        float x3 = y.w * (z.w / (1.f + expf(-z.w)));
        v[k] = make_float4(x0, x1, x2, x3);
        ss += x0 * x0 + x1 * x1 + x2 * x2 + x3 * x3;
    }
    __shared__ float red[128];
    __shared__ float s_scale;
    red[tid] = ss;
    __syncthreads();
    for (int o = 64; o > 0; o >>= 1) {
        if (tid < o) red[tid] += red[tid + o];
        __syncthreads();
    }
    if (tid == 0) s_scale = rsqrtf(red[0] / (float)IF + 1e-5f);
    __syncthreads();
    float sc = s_scale;
#pragma unroll
    for (int k = 0; k < 3; k++) {
        int i = (tid + k * 128) * 4;
        float4 w = *reinterpret_cast<const float4*>(&nw[i]);
        __half2 h0 = __floats2half2_rn(v[k].x * sc * w.x, v[k].y * sc * w.y);
        __half2 h1 = __floats2half2_rn(v[k].z * sc * w.z, v[k].w * sc * w.w);
        *reinterpret_cast<__half2*>(&g_yh[(size_t)t * IF + i])     = h0;
        *reinterpret_cast<__half2*>(&g_yh[(size_t)t * IF + i + 2]) = h1;
    }
}

// ---------------- host launcher ----------------
extern "C" void kernel_launch(void* const* d_in, const int* in_sizes, int n_in,
                              void* d_out, int out_size) {
    const float* hs   = (const float*)d_in[0];
    const float* inw  = (const float*)d_in[1];
    const float* cw   = (const float*)d_in[2];
    const float* cb   = (const float*)d_in[3];
    const float* dtb  = (const float*)d_in[4];
    const float* alog = (const float*)d_in[5];
    const float* Dp   = (const float*)d_in[6];
    const float* nw   = (const float*)d_in[7];
    const float* ow   = (const float*)d_in[8];
    float* out = (float*)d_out;

    void *p_zx = nullptr, *p_yh = nullptr, *p_hsh = nullptr, *p_inwT = nullptr, *p_owT = nullptr;
    cudaGetSymbolAddress(&p_zx, g_zx);
    cudaGetSymbolAddress(&p_yh, g_yh);
    cudaGetSymbolAddress(&p_hsh, g_hsh);
    cudaGetSymbolAddress(&p_inwT, g_inwT);
    cudaGetSymbolAddress(&p_owT, g_owT);

    int smem_gemm = NSTAGE * 2 * STAGE_H * 2;                 // 61440
    int smem_cs = (64 * CS_SH + 128 * CS_SH) * 2;             // 27648
    int smem_y  = YD_HALVES * 2 + 128 * 4;                    // ~53.8KB
    cudaFuncSetAttribute(f16gemm_kernel, cudaFuncAttributeMaxDynamicSharedMemorySize, smem_gemm);
    cudaFuncSetAttribute(chunkstate_mma_kernel, cudaFuncAttributeMaxDynamicSharedMemorySize, smem_cs);
    cudaFuncSetAttribute(ydiag_mma_kernel, cudaFuncAttributeMaxDynamicSharedMemorySize, smem_y);

    // 0. prep
    round_h_kernel<<<(TTOT * HIDD + 255) / 256, 256>>>(hs, (__half*)p_hsh, TTOT * HIDD);
    {
        dim3 g((NPROJ + 31) / 32, (HIDD + 31) / 32);
        transpose_round_h_kernel<<<g, dim3(32, 8)>>>(inw, (__half*)p_inwT, HIDD, NPROJ);
    }
    {
        dim3 g((HIDD + 31) / 32, (IF + 31) / 32);
        transpose_round_h_kernel<<<g, dim3(32, 8)>>>(ow, (__half*)p_owT, IF, HIDD);
    }

    // 1. in_proj GEMM (fp16)
    {
        dim3 grid((NPROJ + 127) / 128, TTOT / 128);
        f16gemm_kernel<<<grid, 256, smem_gemm>>>((const __half*)p_hsh, (const __half*)p_inwT,
                                                 (float*)p_zx, TTOT, NPROJ, HIDD);
    }
    // 2. conv + silu (8 timesteps/thread)
    conv_kernel<<<(448 * (TTOT / 8)) / 256, 256>>>(cw, cb);
    // 3. cumsum with fused dt softplus
    acum_kernel<<<BSZ * HH * CN, 256>>>(alog, dtb);
    // 4. local chunk states (fp16 mma)
    chunkstate_mma_kernel<<<BSZ * CN * HH, 256, smem_cs>>>();
    // 5. inter-chunk recurrence
    recur_kernel<<<BSZ * HH * 32, 256>>>();
    // 6. Y (fp16 mma, split lt — round-10 best)
    {
        dim3 grid(4, BSZ * CN * HH);
        ydiag_mma_kernel<<<grid, 256, smem_y>>>(Dp);
    }
    // 7. gated RMSNorm (fp16 out)
    gnorm_kernel<<<TTOT, 128>>>(nw);
    // 8. out_proj GEMM (fp16)
    {
        dim3 grid(HIDD / 128, TTOT / 128);
        f16gemm_kernel<<<grid, 256, smem_gemm>>>((const __half*)p_yh, (const __half*)p_owT,
                                                 out, TTOT, HIDD, IF);
    }
}

// round 15
// speedup vs baseline: 1.4098x; 1.1000x over previous
#include <cuda_runtime.h>
#include <cuda_fp16.h>
#include <cuda_bf16.h>
#include <math.h>
#include <stdint.h>

// ---------------- problem constants ----------------
#define BSZ   2
#define LSEQ  4096
#define TTOT  8192          // BSZ*LSEQ
#define HIDD  768
#define IF    1536          // I
#define NST   128           // N
#define HH    24            // H
#define PP    64            // P
#define CSZ   256           // chunk size
#define CN    16            // LSEQ/CSZ
#define KC    4             // conv kernel
#define NPROJ 3352          // 2*(I+N)+H
#define XBCW  1792          // I+2N

// ---------------- scratch (static device globals; no allocs) ----------------
__device__ float  g_zx[TTOT * NPROJ];               // in_proj output (z | xBC | dt)
__device__ __half g_xch[TTOT * XBCW];               // conv+silu output (fp16)
__device__ float  g_dt[TTOT * HH];                  // softplus(dt+bias)
__device__ float  g_ac[BSZ * HH * CN * CSZ];        // per-chunk inclusive cumsum of A*dt
__device__ float  g_ls[BSZ * CN * HH * PP * NST];   // local chunk states (fp32)
__device__ __half g_psh[BSZ * CN * HH * PP * NST];  // prefix states (fp16)
__device__ float  g_y [TTOT * IF];                  // y fp32 (pre-norm)
__device__ __half g_yh [TTOT * IF];                 // y fp16 (post-norm, out_proj A)
__device__ __half g_hsh[TTOT * HIDD];               // hs in fp16
__device__ __half g_inwT[NPROJ * HIDD];             // in_proj_w^T, fp16
__device__ __half g_owT [HIDD * IF];                // out_proj_w^T, fp16

// ---------------- helpers ----------------
__device__ __forceinline__ uint32_t fu(float x) { return __float_as_uint(x); }

__device__ __forceinline__ void mma_f16(float* c, uint32_t a0, uint32_t a1,
                                        uint32_t a2, uint32_t a3,
                                        uint32_t b0, uint32_t b1) {
    asm volatile(
        "mma.sync.aligned.m16n8k16.row.col.f32.f16.f16.f32 "
        "{%0,%1,%2,%3}, {%4,%5,%6,%7}, {%8,%9}, {%0,%1,%2,%3};\n"
        : "+f"(c[0]), "+f"(c[1]), "+f"(c[2]), "+f"(c[3])
        : "r"(a0), "r"(a1), "r"(a2), "r"(a3), "r"(b0), "r"(b1));
}
__device__ __forceinline__ void ldsm_x4(uint32_t addr, uint32_t& r0, uint32_t& r1,
                                        uint32_t& r2, uint32_t& r3) {
    asm volatile("ldmatrix.sync.aligned.m8n8.x4.shared.b16 {%0,%1,%2,%3}, [%4];"
                 : "=r"(r0), "=r"(r1), "=r"(r2), "=r"(r3) : "r"(addr));
}
__device__ __forceinline__ void cpasync16(uint32_t daddr, const void* gaddr, bool pred) {
    int sz = pred ? 16 : 0;
    asm volatile("cp.async.cg.shared.global [%0], [%1], 16, %2;"
                 :: "r"(daddr), "l"(gaddr), "r"(sz));
}
#define CP_COMMIT()  asm volatile("cp.async.commit_group;")
#define CP_WAIT3()   asm volatile("cp.async.wait_group 3;")

#define LDSM_OFF_H(S) ((uint32_t)(((lane & 7) + ((lane >> 3) & 1) * 8) * (S) + (lane >> 4) * 8))

// ================= FP16 GEMM: ldmatrix + cp.async, BK=16, 5 stages, BN=128 =================
#define GSTH 24
#define STAGE_H (128 * GSTH)
#define NSTAGE 5

__global__ __launch_bounds__(256, 2) void f16gemm_kernel(const __half* __restrict__ A,
                                                         const __half* __restrict__ Bt,
                                                         float* __restrict__ C,
                                                         int M, int N, int K) {
    extern __shared__ __half smh[];
    const int tid = threadIdx.x;
    const int lane = tid & 31;
    const int warpId = tid >> 5;
    const int gid = lane >> 2, tig = lane & 3;
    const int warpM = warpId & 1;
    const int warpN = warpId >> 1;
    const int rowBase = blockIdx.y * 128;
    const int colBase = blockIdx.x * 128;
    const int nk = K >> 4;

    uint32_t smBase = (uint32_t)__cvta_generic_to_shared(smh);

    const int cpr = tid >> 1;
    const int cpc = (tid & 1) * 8;
    const int nB = colBase + cpr;
    const bool bOK = nB < N;
    const int nBc = bOK ? nB : 0;
    const uint32_t cpOffB = (uint32_t)(cpr * GSTH + cpc) * 2;

    auto issue = [&](int kt, int stage) {
        int k0 = kt << 4;
        uint32_t sA = smBase + (uint32_t)(stage * 2 * STAGE_H) * 2 + cpOffB;
        uint32_t sB = smBase + (uint32_t)((stage * 2 + 1) * STAGE_H) * 2 + cpOffB;
        const __half* ga = &A[(size_t)(rowBase + cpr) * K + k0 + cpc];
        const __half* gb = &Bt[(size_t)nBc * K + k0 + cpc];
        cpasync16(sA, ga, true);
        cpasync16(sB, gb, bOK);
        CP_COMMIT();
    };

    const uint32_t lOff = LDSM_OFF_H(GSTH);

    float acc[4][4][4];
#pragma unroll
    for (int mt = 0; mt < 4; mt++)
#pragma unroll
        for (int nt = 0; nt < 4; nt++)
#pragma unroll
            for (int e = 0; e < 4; e++) acc[mt][nt][e] = 0.f;

#pragma unroll
    for (int p = 0; p < NSTAGE - 1; p++)
        if (p < nk) issue(p, p);

    for (int kt = 0; kt < nk; kt++) {
        CP_WAIT3();
        __syncthreads();
        if (kt + NSTAGE - 1 < nk) issue(kt + NSTAGE - 1, (kt + NSTAGE - 1) % NSTAGE);

        int stage = kt % NSTAGE;
        uint32_t aBase = smBase + (uint32_t)(stage * 2 * STAGE_H) * 2;
        uint32_t bBase = smBase + (uint32_t)((stage * 2 + 1) * STAGE_H) * 2;

        uint32_t bfr[4][2];
#pragma unroll
        for (int pair = 0; pair < 2; pair++) {
            uint32_t addr = bBase + ((uint32_t)((warpN * 32 + pair * 16) * GSTH) + lOff) * 2;
            uint32_t r0, r1, r2, r3;
            ldsm_x4(addr, r0, r1, r2, r3);
            bfr[pair * 2][0] = r0; bfr[pair * 2][1] = r2;
            bfr[pair * 2 + 1][0] = r1; bfr[pair * 2 + 1][1] = r3;
        }
#pragma unroll
        for (int mt = 0; mt < 4; mt++) {
            uint32_t addr = aBase + ((uint32_t)((warpM * 64 + mt * 16) * GSTH) + lOff) * 2;
            uint32_t a0, a1, a2, a3;
            ldsm_x4(addr, a0, a1, a2, a3);
#pragma unroll
            for (int nt = 0; nt < 4; nt++)
                mma_f16(acc[mt][nt], a0, a1, a2, a3, bfr[nt][0], bfr[nt][1]);
        }
    }

#pragma unroll
    for (int mt = 0; mt < 4; mt++) {
        int r0 = rowBase + warpM * 64 + mt * 16 + gid;
#pragma unroll
        for (int nt = 0; nt < 4; nt++) {
            int c0 = colBase + warpN * 32 + nt * 8 + tig * 2;
            if (c0 < N)     C[(size_t)r0 * N + c0]           = acc[mt][nt][0];
            if (c0 + 1 < N) C[(size_t)r0 * N + c0 + 1]       = acc[mt][nt][1];
            if (c0 < N)     C[(size_t)(r0 + 8) * N + c0]     = acc[mt][nt][2];
            if (c0 + 1 < N) C[(size_t)(r0 + 8) * N + c0 + 1] = acc[mt][nt][3];
        }
    }
}

// ---------------- prep ----------------
__global__ __launch_bounds__(256) void round_h_kernel(const float* __restrict__ src,
                                                      __half* __restrict__ dst, int n) {
    int i = blockIdx.x * 256 + threadIdx.x;
    if (i < n) dst[i] = __float2half(src[i]);
}

__global__ void transpose_round_h_kernel(const float* __restrict__ src,
                                         __half* __restrict__ dst, int R, int Cc) {
    __shared__ float t[32][33];
    int c0 = blockIdx.x * 32, r0 = blockIdx.y * 32;
    int x = c0 + threadIdx.x;
    for (int i = threadIdx.y; i < 32; i += 8) {
        int y = r0 + i;
        if (x < Cc && y < R) t[i][threadIdx.x] = src[(size_t)y * Cc + x];
    }
    __syncthreads();
    int xo = r0 + threadIdx.x;
    for (int i = threadIdx.y; i < 32; i += 8) {
        int yo = c0 + i;
        if (xo < R && yo < Cc) dst[(size_t)yo * R + xo] = __float2half(t[threadIdx.x][i]);
    }
}

// ---------------- conv1d + bias + silu: 8 timesteps per thread, fp16 out ----------------
__global__ __launch_bounds__(256) void conv_kernel(const float* __restrict__ cw,
                                                   const float* __restrict__ cb) {
    int idx = blockIdx.x * 256 + threadIdx.x;          // < 448 * 1024
    int ch4 = idx % 448;
    int lt8 = idx / 448;
    int ch = ch4 * 4;
    int t0 = lt8 * 8;
    int b = t0 / LSEQ, l0 = t0 % LSEQ;

    float4 w[KC];
#pragma unroll
    for (int k = 0; k < KC; k++)
        w[k] = *reinterpret_cast<const float4*>(&cw[k * XBCW + ch]);
    float4 bias = *reinterpret_cast<const float4*>(&cb[ch]);

    float4 xb[11];
#pragma unroll
    for (int j = 0; j < 11; j++) {
        int lp = l0 - 3 + j;
        if (lp >= 0)
            xb[j] = *reinterpret_cast<const float4*>(&g_zx[(size_t)(b * LSEQ + lp) * NPROJ + IF + ch]);
        else
            xb[j] = make_float4(0.f, 0.f, 0.f, 0.f);
    }
#pragma unroll
    for (int i = 0; i < 8; i++) {
        float4 acc = bias;
#pragma unroll
        for (int k = 0; k < KC; k++) {
            float4 xv = xb[i + k];
            acc.x = fmaf(xv.x, w[k].x, acc.x);
            acc.y = fmaf(xv.y, w[k].y, acc.y);
            acc.z = fmaf(xv.z, w[k].z, acc.z);
            acc.w = fmaf(xv.w, w[k].w, acc.w);
        }
        acc.x = acc.x / (1.f + expf(-acc.x));
        acc.y = acc.y / (1.f + expf(-acc.y));
        acc.z = acc.z / (1.f + expf(-acc.z));
        acc.w = acc.w / (1.f + expf(-acc.w));
        __half2 h0 = __floats2half2_rn(acc.x, acc.y);
        __half2 h1 = __floats2half2_rn(acc.z, acc.w);
        uint2 pk = make_uint2(*reinterpret_cast<uint32_t*>(&h0), *reinterpret_cast<uint32_t*>(&h1));
        *reinterpret_cast<uint2*>(&g_xch[(size_t)(t0 + i) * XBCW + ch]) = pk;
    }
}

// ---------------- acum with fused dt softplus ----------------
__global__ __launch_bounds__(256) void acum_kernel(const float* __restrict__ alog,
                                                   const float* __restrict__ dtb) {
    int bx = blockIdx.x;
    int c  = bx % CN;
    int h  = (bx / CN) % HH;
    int b  = bx / (CN * HH);
    int s  = threadIdx.x;
    int t  = b * LSEQ + c * CSZ + s;
    float A = -expf(alog[h]);
    float x = g_zx[(size_t)t * NPROJ + (NPROJ - HH) + h] + dtb[h];
    float sp = (x > 0.f) ? (x + log1pf(expf(-x))) : log1pf(expf(x));
    float dtv = fmaxf(sp, 0.f);
    g_dt[(size_t)t * HH + h] = dtv;
    __shared__ float a[CSZ];
    a[s] = A * dtv;
    __syncthreads();
    for (int off = 1; off < CSZ; off <<= 1) {
        float add = (s >= off) ? a[s - off] : 0.f;
        __syncthreads();
        a[s] += add;
        __syncthreads();
    }
    g_ac[(size_t)((b * HH + h) * CN + c) * CSZ + s] = a[s];
}

// ================= chunk state via FP16 mma + ldmatrix =================
#define CS_SH 72

__global__ __launch_bounds__(256) void chunkstate_mma_kernel() {
    extern __shared__ __half smh[];
    __half* As = smh;                    // 64 x 72
    __half* Bs = smh + 64 * CS_SH;       // 128 x 72

    int bx = blockIdx.x;
    int h = bx % HH;
    int c = (bx / HH) % CN;
    int b = bx / (HH * CN);
    int tid = threadIdx.x, lane = tid & 31, warpId = tid >> 5;
    int gid = lane >> 2, tig = lane & 3;
    int warpM = warpId & 1, warpN = warpId >> 1;
    int acbase = ((b * HH + h) * CN + c) * CSZ;
    int tbase = b * LSEQ + c * CSZ;
    float Asum = g_ac[acbase + CSZ - 1];

    uint32_t smB = (uint32_t)__cvta_generic_to_shared(smh);
    uint32_t asB = smB;
    uint32_t bsB = smB + (uint32_t)(64 * CS_SH) * 2;
    const uint32_t lOff = LDSM_OFF_H(CS_SH);

    float acc[2][4][4];
#pragma unroll
    for (int mt = 0; mt < 2; mt++)
#pragma unroll
        for (int nt = 0; nt < 4; nt++)
#pragma unroll
            for (int e = 0; e < 4; e++) acc[mt][nt][e] = 0.f;

    for (int kt = 0; kt < 4; kt++) {
        for (int i = tid; i < 64 * 64; i += 256) {
            int l = i >> 6, p = i & 63;
            int ts = tbase + kt * 64 + l;
            float v = __half2float(g_xch[(size_t)ts * XBCW + h * PP + p]) * g_dt[(size_t)ts * HH + h];
            As[p * CS_SH + l] = __float2half(v);
        }
        for (int i = tid; i < 64 * 128; i += 256) {
            int l = i >> 7, n = i & 127;
            int ts = tbase + kt * 64 + l;
            float dec = expf(Asum - g_ac[acbase + kt * 64 + l]);
            Bs[n * CS_SH + l] = __float2half(__half2float(g_xch[(size_t)ts * XBCW + IF + n]) * dec);
        }
        __syncthreads();
#pragma unroll
        for (int k16 = 0; k16 < 4; k16++) {
            int k0 = k16 * 16;
            uint32_t af[2][4];
#pragma unroll
            for (int mt = 0; mt < 2; mt++)
                ldsm_x4(asB + ((uint32_t)((warpM * 32 + mt * 16) * CS_SH + k0) + lOff) * 2,
                        af[mt][0], af[mt][1], af[mt][2], af[mt][3]);
#pragma unroll
            for (int p2 = 0; p2 < 2; p2++) {
                uint32_t r0, r1, r2, r3;
                ldsm_x4(bsB + ((uint32_t)((warpN * 32 + p2 * 16) * CS_SH + k0) + lOff) * 2, r0, r1, r2, r3);
#pragma unroll
                for (int mt = 0; mt < 2; mt++) {
                    mma_f16(acc[mt][p2 * 2],     af[mt][0], af[mt][1], af[mt][2], af[mt][3], r0, r2);
                    mma_f16(acc[mt][p2 * 2 + 1], af[mt][0], af[mt][1], af[mt][2], af[mt][3], r1, r3);
                }
            }
        }
        __syncthreads();
    }

    size_t base = ((size_t)((b * CN + c) * HH + h)) * PP * NST;
#pragma unroll
    for (int mt = 0; mt < 2; mt++) {
        int p0 = warpM * 32 + mt * 16 + gid;
#pragma unroll
        for (int nt = 0; nt < 4; nt++) {
            int n0 = warpN * 32 + nt * 8 + tig * 2;
            g_ls[base + (size_t)p0 * NST + n0]           = acc[mt][nt][0];
            g_ls[base + (size_t)p0 * NST + n0 + 1]       = acc[mt][nt][1];
            g_ls[base + (size_t)(p0 + 8) * NST + n0]     = acc[mt][nt][2];
            g_ls[base + (size_t)(p0 + 8) * NST + n0 + 1] = acc[mt][nt][3];
        }
    }
}

// ---------------- inter-chunk recurrence (ps written fp16) ----------------
__global__ __launch_bounds__(256) void recur_kernel() {
    int blk = blockIdx.x;
    int seg = blk & 31;
    int bh  = blk >> 5;
    int b = bh / HH, h = bh % HH;
    int idx = seg * 256 + threadIdx.x;
    float st = 0.f;
#pragma unroll
    for (int c = 0; c < CN; c++) {
        float es = expf(g_ac[(size_t)((b * HH + h) * CN + c) * CSZ + CSZ - 1]);
        size_t base = ((size_t)((b * CN + c) * HH + h)) * PP * NST;
        g_psh[base + idx] = __float2half(st);
        st = fmaf(st, es, g_ls[base + idx]);
    }
}

// ================= Y via FP16 mma + ldmatrix =================
#define YH_CS 136
#define YH_XS 72
#define YH_GS 72
#define YD_HALVES (64 * YH_CS * 2 + 64 * YH_XS + 64 * YH_GS)

__global__ __launch_bounds__(256) void ydiag_mma_kernel(const float* __restrict__ Darr) {
    extern __shared__ __half smh[];
    __half* Cs  = smh;                        // 64 x 136
    __half* Bst = Cs + 64 * YH_CS;            // 64 x 136
    __half* Xs  = Bst + 64 * YH_CS;           // 64 x 72 ([p][s])
    __half* Gs  = Xs + 64 * YH_XS;            // 64 x 72
    float* aL  = reinterpret_cast<float*>(Gs + 64 * YH_GS);
    float* aS  = aL + 64;

    int lt  = blockIdx.x;
    int bch = blockIdx.y;
    int h = bch % HH;
    int c = (bch / HH) % CN;
    int b = bch / (HH * CN);
    int tid = threadIdx.x, lane = tid & 31, warpId = tid >> 5;
    int gid = lane >> 2, tig = lane & 3;
    int m0 = (warpId & 3) * 16;
    int n0 = (warpId >> 2) * 32;
    int acbase = ((b * HH + h) * CN + c) * CSZ;
    int tbase = b * LSEQ + c * CSZ;

    uint32_t smB = (uint32_t)__cvta_generic_to_shared(smh);
    uint32_t csB  = smB;
    uint32_t bstB = smB + (uint32_t)(64 * YH_CS) * 2;
    uint32_t xsB  = bstB + (uint32_t)(64 * YH_CS) * 2;
    uint32_t gsB  = xsB + (uint32_t)(64 * YH_XS) * 2;

    const uint32_t lOff136 = LDSM_OFF_H(YH_CS);
    const uint32_t lOff72  = LDSM_OFF_H(YH_XS);

    // C tile: direct fp16 copy, 8 halves per load
    for (int i = tid; i < 64 * 16; i += 256) {
        int l = i >> 4, ch = i & 15;
        uint4 v = *reinterpret_cast<const uint4*>(&g_xch[(size_t)(tbase + lt * 64 + l) * XBCW + IF + NST + ch * 8]);
        *reinterpret_cast<uint4*>(&Cs[l * YH_CS + ch * 8]) = v;
    }
    if (tid < 64) aL[tid] = g_ac[acbase + lt * 64 + tid];

    float accD[4][4];
#pragma unroll
    for (int nt = 0; nt < 4; nt++)
#pragma unroll
        for (int e = 0; e < 4; e++) accD[nt][e] = 0.f;

    for (int st = 0; st <= lt; st++) {
        __syncthreads();
        for (int i = tid; i < 64 * 16; i += 256) {
            int s = i >> 4, ch = i & 15;
            uint4 v = *reinterpret_cast<const uint4*>(&g_xch[(size_t)(tbase + st * 64 + s) * XBCW + IF + ch * 8]);
            *reinterpret_cast<uint4*>(&Bst[s * YH_CS + ch * 8]) = v;
        }
        for (int i = tid; i < 64 * 64; i += 256) {
            int s = i >> 6, p = i & 63;
            int ts = tbase + st * 64 + s;
            Xs[p * YH_XS + s] = __float2half(
                __half2float(g_xch[(size_t)ts * XBCW + h * PP + p]) * g_dt[(size_t)ts * HH + h]);
        }
        if (tid < 64) aS[tid] = g_ac[acbase + st * 64 + tid];
        __syncthreads();

        float g4[4][4];
#pragma unroll
        for (int nt = 0; nt < 4; nt++)
#pragma unroll
            for (int e = 0; e < 4; e++) g4[nt][e] = 0.f;
#pragma unroll
        for (int k16 = 0; k16 < 8; k16++) {
            int k0 = k16 * 16;
            uint32_t a0, a1, a2, a3;
            ldsm_x4(csB + ((uint32_t)(m0 * YH_CS + k0) + lOff136) * 2, a0, a1, a2, a3);
#pragma unroll
            for (int p2 = 0; p2 < 2; p2++) {
                uint32_t r0, r1, r2, r3;
                ldsm_x4(bstB + ((uint32_t)((n0 + p2 * 16) * YH_CS + k0) + lOff136) * 2, r0, r1, r2, r3);
                mma_f16(g4[p2 * 2],     a0, a1, a2, a3, r0, r2);
                mma_f16(g4[p2 * 2 + 1], a0, a1, a2, a3, r1, r3);
            }
        }
        {
            int lA = m0 + gid, lB = lA + 8;
            int glA = lt * 64 + lA, glB = glA + 8;
            float aLA = aL[lA], aLB = aL[lB];
#pragma unroll
            for (int nt = 0; nt < 4; nt++) {
                int s0 = n0 + nt * 8 + tig * 2;
                int gs0 = st * 64 + s0;
                float as0 = aS[s0], as1 = aS[s0 + 1];
                float v0 = (gs0     <= glA) ? g4[nt][0] * expf(aLA - as0) : 0.f;
                float v1 = (gs0 + 1 <= glA) ? g4[nt][1] * expf(aLA - as1) : 0.f;
                float v2 = (gs0     <= glB) ? g4[nt][2] * expf(aLB - as0) : 0.f;
                float v3 = (gs0 + 1 <= glB) ? g4[nt][3] * expf(aLB - as1) : 0.f;
                *reinterpret_cast<__half2*>(&Gs[lA * YH_GS + s0]) = __floats2half2_rn(v0, v1);
                *reinterpret_cast<__half2*>(&Gs[lB * YH_GS + s0]) = __floats2half2_rn(v2, v3);
            }
        }
        __syncthreads();
#pragma unroll
        for (int k16 = 0; k16 < 4; k16++) {
            int k0 = k16 * 16;
            uint32_t a0, a1, a2, a3;
            ldsm_x4(gsB + ((uint32_t)(m0 * YH_GS + k0) + lOff72) * 2, a0, a1, a2, a3);
#pragma unroll
            for (int p2 = 0; p2 < 2; p2++) {
                uint32_t r0, r1, r2, r3;
                ldsm_x4(xsB + ((uint32_t)((n0 + p2 * 16) * YH_XS + k0) + lOff72) * 2, r0, r1, r2, r3);
                mma_f16(accD[p2 * 2],     a0, a1, a2, a3, r0, r2);
                mma_f16(accD[p2 * 2 + 1], a0, a1, a2, a3, r1, r3);
            }
        }
    }

    __syncthreads();
    {
        size_t sbase = ((size_t)((b * CN + c) * HH + h)) * PP * NST;
        for (int i = tid; i < 64 * 16; i += 256) {
            int p = i >> 4, ch = i & 15;
            uint4 v = *reinterpret_cast<const uint4*>(&g_psh[sbase + (size_t)p * NST + ch * 8]);
            *reinterpret_cast<uint4*>(&Bst[p * YH_CS + ch * 8]) = v;
        }
    }
    __syncthreads();
    float off4[4][4];
#pragma unroll
    for (int nt = 0; nt < 4; nt++)
#pragma unroll
        for (int e = 0; e < 4; e++) off4[nt][e] = 0.f;
#pragma unroll
    for (int k16 = 0; k16 < 8; k16++) {
        int k0 = k16 * 16;
        uint32_t a0, a1, a2, a3;
        ldsm_x4(csB + ((uint32_t)(m0 * YH_CS + k0) + lOff136) * 2, a0, a1, a2, a3);
#pragma unroll
        for (int p2 = 0; p2 < 2; p2++) {
            uint32_t r0, r1, r2, r3;
            ldsm_x4(bstB + ((uint32_t)((n0 + p2 * 16) * YH_CS + k0) + lOff136) * 2, r0, r1, r2, r3);
            mma_f16(off4[p2 * 2],     a0, a1, a2, a3, r0, r2);
            mma_f16(off4[p2 * 2 + 1], a0, a1, a2, a3, r1, r3);
        }
    }

    {
        int lA = m0 + gid, lB = lA + 8;
        float e0 = expf(aL[lA]), e1 = expf(aL[lB]);
        float Dh = Darr[h];
        int tA = tbase + lt * 64 + lA;
        int tB = tbase + lt * 64 + lB;
#pragma unroll
        for (int nt = 0; nt < 4; nt++) {
            int p0 = n0 + nt * 8 + tig * 2;
            float xA0 = __half2float(g_xch[(size_t)tA * XBCW + h * PP + p0]);
            float xA1 = __half2float(g_xch[(size_t)tA * XBCW + h * PP + p0 + 1]);
            float xB0 = __half2float(g_xch[(size_t)tB * XBCW + h * PP + p0]);
            float xB1 = __half2float(g_xch[(size_t)tB * XBCW + h * PP + p0 + 1]);
            g_y[(size_t)tA * IF + h * PP + p0]     = accD[nt][0] + e0 * off4[nt][0] + Dh * xA0;
            g_y[(size_t)tA * IF + h * PP + p0 + 1] = accD[nt][1] + e0 * off4[nt][1] + Dh * xA1;
            g_y[(size_t)tB * IF + h * PP + p0]     = accD[nt][2] + e1 * off4[nt][2] + Dh * xB0;
            g_y[(size_t)tB * IF + h * PP + p0 + 1] = accD[nt][3] + e1 * off4[nt][3] + Dh * xB1;
        }
    }
}

// ---------------- gated RMSNorm (float4 in, fp16 out) ----------------
__global__ __launch_bounds__(128) void gnorm_kernel(const float* __restrict__ nw) {
    int t = blockIdx.x;
    int tid = threadIdx.x;
    float4 v[3];
    float ss = 0.f;
#pragma unroll
    for (int k = 0; k < 3; k++) {
        int i = (tid + k * 128) * 4;
        float4 y = *reinterpret_cast<const float4*>(&g_y[(size_t)t * IF + i]);
        float4 z = *reinterpret_cast<const float4*>(&g_zx[(size_t)t * NPROJ + i]);
        float x0 = y.x * (z.x / (1.f + expf(-z.x)));
        float x1 = y.y * (z.y / (1.f + expf(-z.y)));
        float x2 = y.z * (z.z / (1.f + expf(-z.z)));
        float x3 = y.w * (z.w / (1.f + expf(-z.w)));
        v[k] = make_float4(x0, x1, x2, x3);
        ss += x0 * x0 + x1 * x1 + x2 * x2 + x3 * x3;
    }
    __shared__ float red[128];
    __shared__ float s_scale;
    red[tid] = ss;
    __syncthreads();
    for (int o = 64; o > 0; o >>= 1) {
        if (tid < o) red[tid] += red[tid + o];
        __syncthreads();
    }
    if (tid == 0) s_scale = rsqrtf(red[0] / (float)IF + 1e-5f);
    __syncthreads();
    float sc = s_scale;
#pragma unroll
    for (int k = 0; k < 3; k++) {
        int i = (tid + k * 128) * 4;
        float4 w = *reinterpret_cast<const float4*>(&nw[i]);
        __half2 h0 = __floats2half2_rn(v[k].x * sc * w.x, v[k].y * sc * w.y);
        __half2 h1 = __floats2half2_rn(v[k].z * sc * w.z, v[k].w * sc * w.w);
        *reinterpret_cast<__half2*>(&g_yh[(size_t)t * IF + i])     = h0;
        *reinterpret_cast<__half2*>(&g_yh[(size_t)t * IF + i + 2]) = h1;
    }
}

// ---------------- host launcher ----------------
extern "C" void kernel_launch(void* const* d_in, const int* in_sizes, int n_in,
                              void* d_out, int out_size) {
    const float* hs   = (const float*)d_in[0];
    const float* inw  = (const float*)d_in[1];
    const float* cw   = (const float*)d_in[2];
    const float* cb   = (const float*)d_in[3];
    const float* dtb  = (const float*)d_in[4];
    const float* alog = (const float*)d_in[5];
    const float* Dp   = (const float*)d_in[6];
    const float* nw   = (const float*)d_in[7];
    const float* ow   = (const float*)d_in[8];
    float* out = (float*)d_out;

    void *p_zx = nullptr, *p_yh = nullptr, *p_hsh = nullptr, *p_inwT = nullptr, *p_owT = nullptr;
    cudaGetSymbolAddress(&p_zx, g_zx);
    cudaGetSymbolAddress(&p_yh, g_yh);
    cudaGetSymbolAddress(&p_hsh, g_hsh);
    cudaGetSymbolAddress(&p_inwT, g_inwT);
    cudaGetSymbolAddress(&p_owT, g_owT);

    int smem_gemm = NSTAGE * 2 * STAGE_H * 2;                 // 61440
    int smem_cs = (64 * CS_SH + 128 * CS_SH) * 2;             // 27648
    int smem_y  = YD_HALVES * 2 + 128 * 4;                    // ~53.8KB
    cudaFuncSetAttribute(f16gemm_kernel, cudaFuncAttributeMaxDynamicSharedMemorySize, smem_gemm);
    cudaFuncSetAttribute(chunkstate_mma_kernel, cudaFuncAttributeMaxDynamicSharedMemorySize, smem_cs);
    cudaFuncSetAttribute(ydiag_mma_kernel, cudaFuncAttributeMaxDynamicSharedMemorySize, smem_y);

    // 0. prep
    round_h_kernel<<<(TTOT * HIDD + 255) / 256, 256>>>(hs, (__half*)p_hsh, TTOT * HIDD);
    {
        dim3 g((NPROJ + 31) / 32, (HIDD + 31) / 32);
        transpose_round_h_kernel<<<g, dim3(32, 8)>>>(inw, (__half*)p_inwT, HIDD, NPROJ);
    }
    {
        dim3 g((HIDD + 31) / 32, (IF + 31) / 32);
        transpose_round_h_kernel<<<g, dim3(32, 8)>>>(ow, (__half*)p_owT, IF, HIDD);
    }

    // 1. in_proj GEMM (fp16)
    {
        dim3 grid((NPROJ + 127) / 128, TTOT / 128);
        f16gemm_kernel<<<grid, 256, smem_gemm>>>((const __half*)p_hsh, (const __half*)p_inwT,
                                                 (float*)p_zx, TTOT, NPROJ, HIDD);
    }
    // 2. conv + silu (fp16 out)
    conv_kernel<<<(448 * (TTOT / 8)) / 256, 256>>>(cw, cb);
    // 3. cumsum with fused dt softplus
    acum_kernel<<<BSZ * HH * CN, 256>>>(alog, dtb);
    // 4. local chunk states (fp16 mma)
    chunkstate_mma_kernel<<<BSZ * CN * HH, 256, smem_cs>>>();
    // 5. inter-chunk recurrence (fp16 ps)
    recur_kernel<<<BSZ * HH * 32, 256>>>();
    // 6. Y (fp16 mma, split lt)
    {
        dim3 grid(4, BSZ * CN * HH);
        ydiag_mma_kernel<<<grid, 256, smem_y>>>(Dp);
    }
    // 7. gated RMSNorm (fp16 out)
    gnorm_kernel<<<TTOT, 128>>>(nw);
    // 8. out_proj GEMM (fp16)
    {
        dim3 grid(HIDD / 128, TTOT / 128);
        f16gemm_kernel<<<grid, 256, smem_gemm>>>((const __half*)p_yh, (const __half*)p_owT,
                                                 out, TTOT, HIDD, IF);
    }
}